// round 16
// baseline (speedup 1.0000x reference)
#include <cuda_runtime.h>
#include <cuda_bf16.h>
#include <cstdint>
#include <cmath>

#define NROWS 8192
#define BHALF 4096
#define DDIM  512
#define INV_T 14.285714285714286f
// log2(e)/T
#define EXP_SCALE 20.60992915555662f
#define SPANS 256              // one partial per 32-col span (collision-free)
#define SROW 40                // padded smem row (bf16 units): 80B, conflict-free
#define NTILES 2080            // 64*65/2 upper-triangle 128x128 tiles
#define GRID (NTILES * 2)      // two 64-row half-tiles per tile
#define STAGE_ROWS 192         // 64 A rows + 128 B rows
#define STAGE_B (STAGE_ROWS * SROW * 2)   // 15360 bytes per stage
#define SMEM_BYTES (3 * STAGE_B)          // 46080 (3-stage: proven optimum)
#define RBLOCKS 1024

// ---------------- device scratch (no allocation allowed) ----------------
__device__ __nv_bfloat16 g_fb16[(size_t)NROWS * DDIM];      // 8 MB normalized bf16
__device__ float         g_partial[(size_t)NROWS * SPANS];  // 8 MB [row][span]
__device__ float         g_pos [NROWS];
__device__ float         g_blocksum[RBLOCKS];
__device__ unsigned      g_cnt;                             // zero-init, self-resetting

// ---------------- PTX helpers (plain sm_103-legal only) ----------------
__device__ __forceinline__ uint32_t smem_u32(const void* p) {
    uint32_t a;
    asm("{ .reg .u64 t; cvta.to.shared.u64 t, %1; cvt.u32.u64 %0, t; }" : "=r"(a) : "l"(p));
    return a;
}

__device__ __forceinline__ void cp16(uint32_t s, const void* g) {
    asm volatile("cp.async.cg.shared.global [%0], [%1], 16;" :: "r"(s), "l"(g) : "memory");
}
__device__ __forceinline__ void cp_commit() {
    asm volatile("cp.async.commit_group;" ::: "memory");
}
template<int N> __device__ __forceinline__ void cp_wait() {
    asm volatile("cp.async.wait_group %0;" :: "n"(N) : "memory");
}

__device__ __forceinline__ void ldsm_x4(uint32_t* r, uint32_t addr) {
    asm volatile("ldmatrix.sync.aligned.m8n8.x4.shared.b16 {%0,%1,%2,%3}, [%4];"
                 : "=r"(r[0]), "=r"(r[1]), "=r"(r[2]), "=r"(r[3]) : "r"(addr));
}

__device__ __forceinline__ void mma16816(float* c, const uint32_t* a, uint32_t b0, uint32_t b1) {
    asm volatile(
        "mma.sync.aligned.m16n8k16.row.col.f32.bf16.bf16.f32 "
        "{%0,%1,%2,%3}, {%4,%5,%6,%7}, {%8,%9}, {%0,%1,%2,%3};"
        : "+f"(c[0]), "+f"(c[1]), "+f"(c[2]), "+f"(c[3])
        : "r"(a[0]), "r"(a[1]), "r"(a[2]), "r"(a[3]), "r"(b0), "r"(b1));
}

__device__ __forceinline__ float ex2f(float x) {
    float y;
    asm("ex2.approx.ftz.f32 %0, %1;" : "=f"(y) : "f"(x));
    return y;
}

// ---- kernel 1: fused normalize + positives, warp-per-pair (proven best) -------
__global__ void __launch_bounds__(256) norm_pos_kernel(
        const float* __restrict__ logits, const float* __restrict__ label) {
    int i = blockIdx.x * 8 + (threadIdx.x >> 5);
    int lane = threadIdx.x & 31;
    const float4* ap = (const float4*)(logits + (size_t)i * DDIM);
    const float4* bp = (const float4*)(label  + (size_t)i * DDIM);

    float4 av[4], bv[4];
    float ssa = 0.f, ssb = 0.f, ab = 0.f;
    #pragma unroll
    for (int j = 0; j < 4; j++) {
        av[j] = ap[lane + 32 * j];
        bv[j] = bp[lane + 32 * j];
        ssa += av[j].x * av[j].x + av[j].y * av[j].y + av[j].z * av[j].z + av[j].w * av[j].w;
        ssb += bv[j].x * bv[j].x + bv[j].y * bv[j].y + bv[j].z * bv[j].z + bv[j].w * bv[j].w;
        ab  += av[j].x * bv[j].x + av[j].y * bv[j].y + av[j].z * bv[j].z + av[j].w * bv[j].w;
    }
    #pragma unroll
    for (int o = 16; o; o >>= 1) {
        ssa += __shfl_xor_sync(0xffffffffu, ssa, o);
        ssb += __shfl_xor_sync(0xffffffffu, ssb, o);
        ab  += __shfl_xor_sync(0xffffffffu, ab, o);
    }
    float sa = 1.0f / fmaxf(sqrtf(ssa), 1e-12f);
    float sb = 1.0f / fmaxf(sqrtf(ssb), 1e-12f);

    uint2* oa = (uint2*)(g_fb16 + (size_t)i * DDIM);
    uint2* ob = (uint2*)(g_fb16 + (size_t)(i + BHALF) * DDIM);
    #pragma unroll
    for (int j = 0; j < 4; j++) {
        __nv_bfloat162 h0, h1;
        uint2 pk;
        h0.x = __float2bfloat16(av[j].x * sa); h0.y = __float2bfloat16(av[j].y * sa);
        h1.x = __float2bfloat16(av[j].z * sa); h1.y = __float2bfloat16(av[j].w * sa);
        pk.x = *reinterpret_cast<uint32_t*>(&h0);
        pk.y = *reinterpret_cast<uint32_t*>(&h1);
        oa[lane + 32 * j] = pk;
        h0.x = __float2bfloat16(bv[j].x * sb); h0.y = __float2bfloat16(bv[j].y * sb);
        h1.x = __float2bfloat16(bv[j].z * sb); h1.y = __float2bfloat16(bv[j].w * sb);
        pk.x = *reinterpret_cast<uint32_t*>(&h0);
        pk.y = *reinterpret_cast<uint32_t*>(&h1);
        ob[lane + 32 * j] = pk;
    }
    if (lane == 0) {
        float p = ab * sa * sb * INV_T;
        g_pos[i] = p;
        g_pos[i + BHALF] = p;
    }
}

// ---------------- kernel 2: 64x128 half-tiles of the symmetric sim matrix ------
// blockIdx = 2*u + h: tile u (upper triangle, rt<=ct), row half h. 4 warps,
// warp tile 64x32 (warp_n = col quarter). Same kc=32 / 3-stage / wait<1>
// pipeline as the proven config; halved acc -> 3-4 CTAs/SM for latency hiding.
__global__ void __launch_bounds__(128) sim_kernel() {
    extern __shared__ char smem[];

    int tid = threadIdx.x;
    int warp_n = tid >> 5, lane = tid & 31;
    int g = lane >> 2, t = lane & 3;

    int u2 = blockIdx.x;
    int u = u2 >> 1, h = u2 & 1;
    int rt = (int)((129.0 - sqrt(129.0 * 129.0 - 8.0 * (double)u)) * 0.5);
    while (64 * (rt + 1) - ((rt + 1) * rt) / 2 <= u) rt++;
    while (64 * rt - (rt * (rt - 1)) / 2 > u) rt--;
    int ct = rt + (u - (64 * rt - (rt * (rt - 1)) / 2));
    bool diag = (rt == ct);

    const __nv_bfloat16* Ag = g_fb16 + (size_t)(rt * 128 + h * 64) * DDIM;  // 64 rows
    const __nv_bfloat16* Bg = g_fb16 + (size_t)ct * 128 * DDIM;             // 128 rows

    float acc[4][4][4];
    #pragma unroll
    for (int mf = 0; mf < 4; mf++)
        #pragma unroll
        for (int nf = 0; nf < 4; nf++)
            #pragma unroll
            for (int j = 0; j < 4; j++) acc[mf][nf][j] = 0.f;

    uint32_t sbase = smem_u32(smem);

    // issue one 32-wide K chunk into stage `s`: 192 rows (64 A + 128 B)
    auto issue = [&](int s, int kc) {
        uint32_t st = sbase + (uint32_t)s * STAGE_B;
        #pragma unroll
        for (int i = 0; i < 6; i++) {
            int idx = tid + 128 * i;        // 0..767
            int row = idx >> 2, seg = idx & 3;
            const __nv_bfloat16* src = (row < 64)
                ? Ag + (size_t)row * DDIM + kc * 32 + seg * 8
                : Bg + (size_t)(row - 64) * DDIM + kc * 32 + seg * 8;
            cp16(st + (uint32_t)(row * SROW + seg * 8) * 2, src);
        }
        cp_commit();
    };

    issue(0, 0);
    issue(1, 1);

    for (int kc = 0; kc < 16; kc++) {
        cp_wait<1>();          // stage kc landed
        __syncthreads();       // everyone done reading stage being overwritten
        if (kc + 2 < 16) issue((kc + 2) % 3, kc + 2);
        else cp_commit();      // empty group keeps wait_group accounting exact

        uint32_t aBase = sbase + (uint32_t)(kc % 3) * STAGE_B;
        uint32_t bBase = aBase + 64 * SROW * 2;

        #pragma unroll
        for (int ks = 0; ks < 2; ks++) {
            // A frags: 4 x ldmatrix.x4 (mf = 0..3 covers all 64 rows)
            uint32_t afr[4][4];
            {
                int mrow = lane & 7;
                int msel = lane >> 3;                 // 0..3
                int rofs = (msel & 1) * 8 + mrow;
                int cofs = ks * 16 + (msel >> 1) * 8;
                #pragma unroll
                for (int mf = 0; mf < 4; mf++) {
                    int row = mf * 16 + rofs;
                    ldsm_x4(afr[mf], aBase + (uint32_t)(row * SROW + cofs) * 2);
                }
            }
            // B frags: 2 x ldmatrix.x4, each covers 2 nf (32 cols total)
            {
                int mrow = lane & 7;
                int msel = lane >> 3;
                int rofs = (msel >> 1) * 8 + mrow;
                int cofs = ks * 16 + (msel & 1) * 8;
                #pragma unroll
                for (int np = 0; np < 2; np++) {
                    uint32_t r4[4];
                    int row = warp_n * 32 + np * 16 + rofs;
                    ldsm_x4(r4, bBase + (uint32_t)(row * SROW + cofs) * 2);
                    #pragma unroll
                    for (int mf = 0; mf < 4; mf++) {
                        mma16816(acc[mf][np * 2],     afr[mf], r4[0], r4[1]);
                        mma16816(acc[mf][np * 2 + 1], afr[mf], r4[2], r4[3]);
                    }
                }
            }
        }
    }

    // -------- epilogue: exp, diag mask, row sums + (off-diag) split col sums ---
    int rbase = rt * 128 + h * 64;
    int cbase = ct * 128 + warp_n * 32;
    float rs[4][2];
    #pragma unroll
    for (int mf = 0; mf < 4; mf++) { rs[mf][0] = 0.f; rs[mf][1] = 0.f; }

    #pragma unroll
    for (int nf = 0; nf < 4; nf++) {
        float clo0 = 0.f, clo1 = 0.f, chi0 = 0.f, chi1 = 0.f;
        int c0 = cbase + nf * 8 + 2 * t;
        #pragma unroll
        for (int mf = 0; mf < 4; mf++) {
            const float* c = acc[mf][nf];
            float e0 = ex2f(c[0] * EXP_SCALE);
            float e1 = ex2f(c[1] * EXP_SCALE);
            float e2 = ex2f(c[2] * EXP_SCALE);
            float e3 = ex2f(c[3] * EXP_SCALE);
            if (diag) {
                int r0 = rbase + mf * 16 + g;
                if (c0     == r0)     e0 = 0.f;
                if (c0 + 1 == r0)     e1 = 0.f;
                if (c0     == r0 + 8) e2 = 0.f;
                if (c0 + 1 == r0 + 8) e3 = 0.f;
            }
            rs[mf][0] += e0 + e1;
            rs[mf][1] += e2 + e3;
            if (mf < 2) { clo0 += e0 + e2; clo1 += e1 + e3; }
            else        { chi0 += e0 + e2; chi1 += e1 + e3; }
        }
        if (!diag) {
            #pragma unroll
            for (int o = 4; o <= 16; o <<= 1) {
                clo0 += __shfl_xor_sync(0xffffffffu, clo0, o);
                clo1 += __shfl_xor_sync(0xffffffffu, clo1, o);
                chi0 += __shfl_xor_sync(0xffffffffu, chi0, o);
                chi1 += __shfl_xor_sync(0xffffffffu, chi1, o);
            }
            if (g == 0) {
                int span_lo = rt * 4 + h * 2;          // rows rbase..rbase+31
                int span_hi = span_lo + 1;             // rows rbase+32..rbase+63
                g_partial[(size_t)c0 * SPANS + span_lo]       = clo0;
                g_partial[(size_t)(c0 + 1) * SPANS + span_lo] = clo1;
                g_partial[(size_t)c0 * SPANS + span_hi]       = chi0;
                g_partial[(size_t)(c0 + 1) * SPANS + span_hi] = chi1;
            }
        }
    }
    #pragma unroll
    for (int mf = 0; mf < 4; mf++) {
        float s0 = rs[mf][0], s1 = rs[mf][1];
        s0 += __shfl_xor_sync(0xffffffffu, s0, 1);
        s0 += __shfl_xor_sync(0xffffffffu, s0, 2);
        s1 += __shfl_xor_sync(0xffffffffu, s1, 1);
        s1 += __shfl_xor_sync(0xffffffffu, s1, 2);
        if (t == 0) {
            int r0 = rbase + mf * 16 + g;
            int span = ct * 4 + warp_n;       // row sums, 32-col span
            g_partial[(size_t)r0 * SPANS + span]       = s0;
            g_partial[(size_t)(r0 + 8) * SPANS + span] = s1;
        }
    }
}

// ---- kernel 3: fused per-row lse - pos + grid-wide mean (last-block pattern) --
__global__ void __launch_bounds__(256) reduce_kernel(float* __restrict__ out) {
    int tid = threadIdx.x;
    int warp = tid >> 5, lane = tid & 31;
    int row = blockIdx.x * 8 + warp;
    const float4* p4 = (const float4*)(g_partial + (size_t)row * SPANS);
    float4 v0 = p4[lane], v1 = p4[lane + 32];
    float s = ((v0.x + v0.y) + (v0.z + v0.w)) + ((v1.x + v1.y) + (v1.z + v1.w));
    #pragma unroll
    for (int o = 16; o; o >>= 1) s += __shfl_xor_sync(0xffffffffu, s, o);

    __shared__ float ws[8];
    __shared__ int lastFlag;
    if (lane == 0) ws[warp] = logf(s) - g_pos[row];
    __syncthreads();
    if (tid == 0) {
        float bs = 0.f;
        #pragma unroll
        for (int i = 0; i < 8; i++) bs += ws[i];
        g_blocksum[blockIdx.x] = bs;
        __threadfence();
        unsigned old = atomicAdd(&g_cnt, 1u);
        lastFlag = (old == RBLOCKS - 1);
    }
    __syncthreads();
    if (lastFlag) {
        float a = 0.f;
        #pragma unroll
        for (int i = 0; i < RBLOCKS / 256; i++) a += g_blocksum[tid + 256 * i];
        #pragma unroll
        for (int o = 16; o; o >>= 1) a += __shfl_xor_sync(0xffffffffu, a, o);
        __shared__ float fs[8];
        if (lane == 0) fs[warp] = a;
        __syncthreads();
        if (tid == 0) {
            float tot = 0.f;
            #pragma unroll
            for (int i = 0; i < 8; i++) tot += fs[i];
            out[0] = tot * (1.0f / (float)NROWS);
            g_cnt = 0;     // reset for next graph replay
        }
    }
}

// ---------------- launch ----------------
extern "C" void kernel_launch(void* const* d_in, const int* in_sizes, int n_in,
                              void* d_out, int out_size) {
    const float* logits = (const float*)d_in[0];
    const float* label  = (const float*)d_in[1];
    float* out = (float*)d_out;

    cudaFuncSetAttribute(sim_kernel, cudaFuncAttributeMaxDynamicSharedMemorySize,
                         SMEM_BYTES);

    norm_pos_kernel<<<BHALF / 8, 256>>>(logits, label);
    sim_kernel<<<GRID, 128, SMEM_BYTES>>>();
    reduce_kernel<<<RBLOCKS, 256>>>(out);
}